// round 5
// baseline (speedup 1.0000x reference)
#include <cuda_runtime.h>
#include <cuda_bf16.h>

#define NGRIDC 10000
#define NSTEPC 365
#define NMULC  16
#define NEARZEROF 1e-5f

// One chain = one (grid, mul) HBV state machine.
struct Chain {
    float SNOWPACK, MELTWATER, SM, SUZ, SLZ;
    float BETA, K0, BETAET;
    float FC, invFC, invLPFC, K1, K2, PERC, UZL, TT;
    float CFMAX, negCFMAXTT;      // melt = fma(CFMAX, Tm, negCFMAXTT)
    float CFRCFMAX, CFRCFMAXTT;   // refr = fma(-CFRCFMAX, Tm, CFRCFMAXTT)
    float CWH, C, RF;
};

__device__ __forceinline__ void load_chain(Chain& c, int g, int m,
                                           const float* __restrict__ praw,
                                           const float* __restrict__ wl,
                                           float acv)
{
    // HBV params from params_raw[364, g, i, m]
    const long pbase = ((long)(364 * NGRIDC + g) * 3) * NMULC + m;
    c.BETA   = 1.0f  + praw[pbase + 0 * NMULC] * 5.0f;
    c.K0     = 0.05f + praw[pbase + 1 * NMULC] * 0.85f;
    c.BETAET = 0.3f  + praw[pbase + 2 * NMULC] * 4.7f;

    // Waterloss params wl[g, i, m]
    const long wbase = (long)g * 13 * NMULC + m;
    float FC   = 50.0f   + wl[wbase +  0 * NMULC] * 950.0f;
    float K1   = 0.01f   + wl[wbase +  1 * NMULC] * 0.49f;
    float K2   = 0.001f  + wl[wbase +  2 * NMULC] * 0.199f;
    float LP   = 0.2f    + wl[wbase +  3 * NMULC] * 0.8f;
    float PERC = 0.0f    + wl[wbase +  4 * NMULC] * 10.0f;
    float UZL  = 0.0f    + wl[wbase +  5 * NMULC] * 100.0f;
    float TT   = -2.5f   + wl[wbase +  6 * NMULC] * 5.0f;
    float CFMAX= 0.5f    + wl[wbase +  7 * NMULC] * 9.5f;
    float CFR  = 0.0f    + wl[wbase +  8 * NMULC] * 0.1f;
    float CWH  = 0.0f    + wl[wbase +  9 * NMULC] * 0.2f;
    float Cpar = 0.0f    + wl[wbase + 10 * NMULC] * 1.0f;
    float TRb  = 0.0f    + wl[wbase + 11 * NMULC] * 20.0f;
    float Ac   = 0.0f    + wl[wbase + 12 * NMULC] * 2500.0f;

    c.FC = FC;
    c.invFC = 1.0f / FC;
    c.invLPFC = 1.0f / (LP * FC);
    c.K1 = K1; c.K2 = K2; c.PERC = PERC; c.UZL = UZL; c.TT = TT;
    c.CFMAX = CFMAX;
    c.negCFMAXTT = -CFMAX * TT;
    c.CFRCFMAX = CFR * CFMAX;
    c.CFRCFMAXTT = CFR * CFMAX * TT;
    c.CWH = CWH; c.C = Cpar;

    float rf = fminf(fmaxf((acv - Ac) * 1e-3f, -1.0f), 1.0f);
    if (acv < 2500.0f) {
        c.RF = rf * TRb;
    } else {
        float e = fmaxf(-(acv - 2500.0f) * 0.02f, -10.0f);
        c.RF = __expf(e) * TRb;
    }

    c.SNOWPACK = 0.001f; c.MELTWATER = 0.001f; c.SM = 0.001f;
    c.SUZ = 0.001f; c.SLZ = 0.001f;
}

__device__ __forceinline__ float hbv_step(Chain& c, float Pm, float Tm, float PETm)
{
    bool warm = (Tm >= c.TT);
    float RAIN = warm ? Pm : 0.0f;
    float SNOW = Pm - RAIN;
    float SNOWPACK = c.SNOWPACK + SNOW;

    float melt = fminf(fmaxf(fmaf(c.CFMAX, Tm, c.negCFMAXTT), 0.0f), SNOWPACK);
    float MELTWATER = c.MELTWATER + melt;
    SNOWPACK -= melt;

    float refr = fminf(fmaxf(fmaf(-c.CFRCFMAX, Tm, c.CFRCFMAXTT), 0.0f), MELTWATER);
    SNOWPACK += refr;
    MELTWATER -= refr;

    float tosoil = fmaxf(fmaf(-c.CWH, SNOWPACK, MELTWATER), 0.0f);
    MELTWATER -= tosoil;

    float sw = fminf(__powf(c.SM * c.invFC, c.BETA), 1.0f);
    float inflow = RAIN + tosoil;
    float recharge = inflow * sw;
    float SM = c.SM + inflow - recharge;
    float excess = fmaxf(SM - c.FC, 0.0f);
    SM -= excess;

    float ef = fminf(__powf(SM * c.invLPFC, c.BETAET), 1.0f);
    float ETact = fminf(SM, PETm * ef);
    SM = fmaxf(SM - ETact, NEARZEROF);

    float cap = fminf(c.SLZ, c.C * c.SLZ * (1.0f - fminf(SM * c.invFC, 1.0f)));
    SM = fmaxf(SM + cap, NEARZEROF);
    float SLZ = fmaxf(c.SLZ - cap, NEARZEROF);

    float SUZ = c.SUZ + recharge + excess;
    float perc = fminf(SUZ, c.PERC);
    SUZ -= perc;
    float Q0 = c.K0 * fmaxf(SUZ - c.UZL, 0.0f);
    SUZ -= Q0;
    float Q1 = c.K1 * SUZ;
    SUZ -= Q1;
    SLZ += perc;
    SLZ = fmaxf(SLZ + c.RF, 0.0f);
    float Q2 = c.K2 * SLZ;
    SLZ -= Q2;

    c.SNOWPACK = SNOWPACK; c.MELTWATER = MELTWATER;
    c.SM = SM; c.SUZ = SUZ; c.SLZ = SLZ;
    return Q0 + Q1 + Q2;
}

// 160000 threads: one chain (grid g, mul m) per thread; tid = g*16 + m.
// 64-thread blocks -> exactly 2500 blocks -> 16-17 blocks/SM (0.6% imbalance)
// = 33.8 warps/SM = 8.4 warps/SMSP for latency hiding.
__global__ __launch_bounds__(64)
void hbv_kernel(const float* __restrict__ x,
                const float* __restrict__ praw,
                const float* __restrict__ wl,
                const float* __restrict__ ac,
                float* __restrict__ out)
{
    int tid = blockIdx.x * 64 + threadIdx.x;
    int g = tid >> 4;
    int m = tid & 15;

    float acv = __ldg(&ac[g]);

    Chain c;
    load_chain(c, g, m, praw, wl, acv);

    const float* __restrict__ xp = x + (long)g * 3;
    const long xstride = (long)NGRIDC * 3;

    // software-pipelined forcing loads (independent of state)
    float Pm = __ldg(xp + 0);
    float Tm = __ldg(xp + 1);
    float Em = __ldg(xp + 2);
    xp += xstride;

    float* __restrict__ op = out + g;

#pragma unroll 1
    for (int t = 0; t < NSTEPC; ++t) {
        float Pn = 0.f, Tn = 0.f, En = 0.f;
        if (t < NSTEPC - 1) {
            Pn = __ldg(xp + 0);
            Tn = __ldg(xp + 1);
            En = __ldg(xp + 2);
        }
        xp += xstride;

        float q = hbv_step(c, Pm, Tm, Em);

        // reduce across the 16 lanes of this grid
        q += __shfl_xor_sync(0xffffffffu, q, 1);
        q += __shfl_xor_sync(0xffffffffu, q, 2);
        q += __shfl_xor_sync(0xffffffffu, q, 4);
        q += __shfl_xor_sync(0xffffffffu, q, 8);

        if (m == 0) *op = q * (1.0f / 16.0f);
        op += NGRIDC;

        Pm = Pn; Tm = Tn; Em = En;
    }
}

extern "C" void kernel_launch(void* const* d_in, const int* in_sizes, int n_in,
                              void* d_out, int out_size)
{
    const float* x = nullptr;     // 365*10000*3    = 10,950,000
    const float* praw = nullptr;  // 365*10000*3*16 = 175,200,000
    const float* wl = nullptr;    // 10000*13*16    = 2,080,000
    const float* ac = nullptr;    // 10000
    for (int i = 0; i < n_in; ++i) {
        long s = (long)in_sizes[i];
        if      (s == 10950000L)   x    = (const float*)d_in[i];
        else if (s == 175200000L)  praw = (const float*)d_in[i];
        else if (s == 2080000L)    wl   = (const float*)d_in[i];
        else if (s == 10000L)      ac   = (const float*)d_in[i];
    }

    const int threads = NGRIDC * NMULC;   // 160000
    const int block = 64;
    const int grid = threads / block;     // 2500 exactly
    hbv_kernel<<<grid, block>>>(x, praw, wl, ac, (float*)d_out);
}

// round 8
// speedup vs baseline: 1.3414x; 1.3414x over previous
#include <cuda_runtime.h>
#include <cuda_bf16.h>

#define NGRIDC 10000
#define NSTEPC 365
#define NMULC  16
#define NEARZEROF 1e-5f

// One chain = one (grid, mul) HBV state machine.
struct Chain {
    float SNOWPACK, MELTWATER, SM, SUZ, SLZ;
    float BETA, K0, BETAET;
    float FC, invFC, invLPFC, oneMinusK1, K2, PERC, UZL, TT;
    float CFMAX, negCFMAXTT;   // a = fmaf(CFMAX, Tm, negCFMAXTT) = CFMAX*(Tm-TT)
    float CFR;                 // refr candidate = CFR * a (cold side)
    float CWH, C, RF;
};

__device__ __forceinline__ void load_chain(Chain& c, int g, int m,
                                           const float* __restrict__ praw,
                                           const float* __restrict__ wl,
                                           float acv)
{
    // HBV params from params_raw[364, g, i, m]
    const long pbase = ((long)(364 * NGRIDC + g) * 3) * NMULC + m;
    c.BETA   = 1.0f  + praw[pbase + 0 * NMULC] * 5.0f;
    c.K0     = 0.05f + praw[pbase + 1 * NMULC] * 0.85f;
    c.BETAET = 0.3f  + praw[pbase + 2 * NMULC] * 4.7f;

    // Waterloss params wl[g, i, m]
    const long wbase = (long)g * 13 * NMULC + m;
    float FC   = 50.0f   + wl[wbase +  0 * NMULC] * 950.0f;
    float K1   = 0.01f   + wl[wbase +  1 * NMULC] * 0.49f;
    float K2   = 0.001f  + wl[wbase +  2 * NMULC] * 0.199f;
    float LP   = 0.2f    + wl[wbase +  3 * NMULC] * 0.8f;
    float PERC = 0.0f    + wl[wbase +  4 * NMULC] * 10.0f;
    float UZL  = 0.0f    + wl[wbase +  5 * NMULC] * 100.0f;
    float TT   = -2.5f   + wl[wbase +  6 * NMULC] * 5.0f;
    float CFMAX= 0.5f    + wl[wbase +  7 * NMULC] * 9.5f;
    float CFR  = 0.0f    + wl[wbase +  8 * NMULC] * 0.1f;
    float CWH  = 0.0f    + wl[wbase +  9 * NMULC] * 0.2f;
    float Cpar = 0.0f    + wl[wbase + 10 * NMULC] * 1.0f;
    float TRb  = 0.0f    + wl[wbase + 11 * NMULC] * 20.0f;
    float Ac   = 0.0f    + wl[wbase + 12 * NMULC] * 2500.0f;

    c.FC = FC;
    c.invFC = 1.0f / FC;
    c.invLPFC = 1.0f / (LP * FC);
    c.oneMinusK1 = 1.0f - K1;
    c.K2 = K2; c.PERC = PERC; c.UZL = UZL; c.TT = TT;
    c.CFMAX = CFMAX;
    c.negCFMAXTT = -CFMAX * TT;
    c.CFR = CFR;
    c.CWH = CWH; c.C = Cpar;

    float rf = fminf(fmaxf((acv - Ac) * 1e-3f, -1.0f), 1.0f);
    if (acv < 2500.0f) {
        c.RF = rf * TRb;
    } else {
        float e = fmaxf(-(acv - 2500.0f) * 0.02f, -10.0f);
        c.RF = __expf(e) * TRb;
    }

    c.SNOWPACK = 0.001f; c.MELTWATER = 0.001f; c.SM = 0.001f;
    c.SUZ = 0.001f; c.SLZ = 0.001f;
}

__device__ __forceinline__ float hbv_step(Chain& c, float Pm, float Tm, float PETm)
{
    // --- snow bucket: melt (warm) and refreeze (cold) are mutually exclusive.
    bool warm = (Tm >= c.TT);
    float SNOW = warm ? 0.0f : Pm;
    float RAIN = warm ? Pm : 0.0f;
    float SNOWPACK = c.SNOWPACK + SNOW;

    float a = fmaf(c.CFMAX, Tm, c.negCFMAXTT);         // CFMAX*(Tm-TT), sign = warm
    float t_warm = fminf(a, SNOWPACK);                  // melt  (>=0)
    float t_cold = fmaxf(c.CFR * a, -c.MELTWATER);      // -refr (<=0)
    float tr = warm ? t_warm : t_cold;                  // net snow->melt transfer
    SNOWPACK -= tr;
    float MELTWATER = c.MELTWATER + tr;

    float tosoil = fmaxf(fmaf(-c.CWH, SNOWPACK, MELTWATER), 0.0f);
    MELTWATER -= tosoil;

    // --- soil moisture
    float sw = fminf(__powf(c.SM * c.invFC, c.BETA), 1.0f);
    float inflow = RAIN + tosoil;
    float SMt = c.SM + inflow;
    float recharge = inflow * sw;
    float SM = SMt - recharge;

    float SMc = fminf(SM, c.FC);         // excess removal via min
    float excess = SM - SMc;
    SM = SMc;

    float ef = fminf(__powf(SM * c.invLPFC, c.BETAET), 1.0f);
    // SM - min(SM, PET*ef) == max(SM - PET*ef, 0); then clamp to NEARZERO
    SM = fmaxf(fmaf(-PETm, ef, SM), NEARZEROF);

    // capillary: C*u <= 1 and SLZ >= 0 => min(SLZ, C*SLZ*u) == C*SLZ*u
    float u = fmaxf(fmaf(-SM, c.invFC, 1.0f), 0.0f);
    float cap = (c.C * u) * c.SLZ;
    SM = fmaxf(SM + cap, NEARZEROF);
    float SLZ = fmaxf(c.SLZ - cap, NEARZEROF);

    // --- routing
    float SUZ0 = c.SUZ + recharge + excess;
    float SUZ1 = fmaxf(SUZ0 - c.PERC, 0.0f);            // SUZ after percolation
    float perc = SUZ0 - SUZ1;                           // == min(SUZ0, PERC)
    float SUZh = fmaxf(SUZ1 - c.UZL, 0.0f);
    float SUZ2 = fmaf(-c.K0, SUZh, SUZ1);               // after Q0
    float SUZ3 = SUZ2 * c.oneMinusK1;                   // after Q1
    float q_suz = SUZ1 - SUZ3;                          // Q0 + Q1

    float SLZ1 = fmaxf(SLZ + perc + c.RF, 0.0f);
    float Q2 = c.K2 * SLZ1;

    c.SNOWPACK = SNOWPACK; c.MELTWATER = MELTWATER;
    c.SM = SM; c.SUZ = SUZ3; c.SLZ = SLZ1 - Q2;
    return q_suz + Q2;
}

// 80000 threads: thread handles muls j and j+8 of grid g; tid = g*8 + j.
// 32-thread blocks -> exactly 2500 blocks -> 16-17 blocks/SM (0.6% imbalance),
// 4.2 warps/SMSP + ILP=2 chains per thread (best measured config).
__global__ __launch_bounds__(32, 17)
void hbv_kernel(const float* __restrict__ x,
                const float* __restrict__ praw,
                const float* __restrict__ wl,
                const float* __restrict__ ac,
                float* __restrict__ out)
{
    int tid = blockIdx.x * 32 + threadIdx.x;
    int g = tid >> 3;
    int j = tid & 7;

    float acv = __ldg(&ac[g]);

    Chain c0, c1;
    load_chain(c0, g, j,     praw, wl, acv);
    load_chain(c1, g, j + 8, praw, wl, acv);

    const float* __restrict__ xp = x + (long)g * 3;
    const long xstride = (long)NGRIDC * 3;

    // software-pipelined forcing loads (independent of state)
    float Pm = __ldg(xp + 0);
    float Tm = __ldg(xp + 1);
    float Em = __ldg(xp + 2);
    xp += xstride;

    float* __restrict__ op = out + g;

#pragma unroll 1
    for (int t = 0; t < NSTEPC; ++t) {
        float Pn = 0.f, Tn = 0.f, En = 0.f;
        if (t < NSTEPC - 1) {
            Pn = __ldg(xp + 0);
            Tn = __ldg(xp + 1);
            En = __ldg(xp + 2);
        }
        xp += xstride;

        float q = hbv_step(c0, Pm, Tm, Em) + hbv_step(c1, Pm, Tm, Em);

        // reduce across the 8 lanes of this grid (2 muls each -> 16 muls)
        q += __shfl_xor_sync(0xffffffffu, q, 1);
        q += __shfl_xor_sync(0xffffffffu, q, 2);
        q += __shfl_xor_sync(0xffffffffu, q, 4);

        if (j == 0) *op = q * (1.0f / 16.0f);
        op += NGRIDC;

        Pm = Pn; Tm = Tn; Em = En;
    }
}

extern "C" void kernel_launch(void* const* d_in, const int* in_sizes, int n_in,
                              void* d_out, int out_size)
{
    const float* x = nullptr;     // 365*10000*3    = 10,950,000
    const float* praw = nullptr;  // 365*10000*3*16 = 175,200,000
    const float* wl = nullptr;    // 10000*13*16    = 2,080,000
    const float* ac = nullptr;    // 10000
    for (int i = 0; i < n_in; ++i) {
        long s = (long)in_sizes[i];
        if      (s == 10950000L)   x    = (const float*)d_in[i];
        else if (s == 175200000L)  praw = (const float*)d_in[i];
        else if (s == 2080000L)    wl   = (const float*)d_in[i];
        else if (s == 10000L)      ac   = (const float*)d_in[i];
    }

    const int threads = NGRIDC * (NMULC / 2);   // 80000
    const int block = 32;
    const int grid = threads / block;           // 2500 exactly
    hbv_kernel<<<grid, block>>>(x, praw, wl, ac, (float*)d_out);
}